// round 3
// baseline (speedup 1.0000x reference)
#include <cuda_runtime.h>
#include <cuda_bf16.h>

#define N_NODES 100000
#define F_IN 256
#define F_OUT 256

// Scratch for support = X @ W  (102.4 MB). Device global per allocation rules.
__device__ float g_support[(size_t)N_NODES * F_OUT];

// ---------------------------------------------------------------------------
// Stage 1: tiled SGEMM  C[M,256] = A[M,256] @ B[256,256]
// BM=64, BN=64, BK=16, 256 threads, each thread computes 4x4.
// ---------------------------------------------------------------------------
#define BM 64
#define BN 64
#define BK 16

__global__ void __launch_bounds__(256) gemm_kernel(
    const float* __restrict__ A,   // [M, 256]
    const float* __restrict__ B,   // [256, 256]
    float* __restrict__ C,         // [M, 256]
    int M)
{
    __shared__ float As[BM][BK];
    __shared__ float Bs[BK][BN];

    const int tid = threadIdx.x;
    const int tx = tid % 16;           // col group
    const int ty = tid / 16;           // row group
    const int blockRow = blockIdx.y * BM;
    const int blockCol = blockIdx.x * BN;

    float acc[4][4];
#pragma unroll
    for (int i = 0; i < 4; i++)
#pragma unroll
        for (int j = 0; j < 4; j++) acc[i][j] = 0.0f;

    for (int k0 = 0; k0 < F_IN; k0 += BK) {
        // Load As: 64x16 = 1024 elems, 4 per thread
#pragma unroll
        for (int l = 0; l < 4; l++) {
            int idx = tid + l * 256;
            int r = idx / BK;
            int c = idx % BK;
            int gr = blockRow + r;
            As[r][c] = (gr < M) ? A[(size_t)gr * F_IN + k0 + c] : 0.0f;
        }
        // Load Bs: 16x64 = 1024 elems
#pragma unroll
        for (int l = 0; l < 4; l++) {
            int idx = tid + l * 256;
            int r = idx / BN;
            int c = idx % BN;
            Bs[r][c] = B[(size_t)(k0 + r) * F_OUT + blockCol + c];
        }
        __syncthreads();

#pragma unroll
        for (int k = 0; k < BK; k++) {
            float ra[4], rb[4];
#pragma unroll
            for (int i = 0; i < 4; i++) ra[i] = As[ty * 4 + i][k];
#pragma unroll
            for (int j = 0; j < 4; j++) rb[j] = Bs[k][tx * 4 + j];
#pragma unroll
            for (int i = 0; i < 4; i++)
#pragma unroll
                for (int j = 0; j < 4; j++)
                    acc[i][j] = fmaf(ra[i], rb[j], acc[i][j]);
        }
        __syncthreads();
    }

#pragma unroll
    for (int i = 0; i < 4; i++) {
        int gr = blockRow + ty * 4 + i;
        if (gr < M) {
#pragma unroll
            for (int j = 0; j < 4; j++) {
                C[(size_t)gr * F_OUT + blockCol + tx * 4 + j] = acc[i][j];
            }
        }
    }
}

// ---------------------------------------------------------------------------
// Stage 2: init out with bias (out is poisoned, must initialize)
// ---------------------------------------------------------------------------
__global__ void bias_init_kernel(float* __restrict__ out,
                                 const float* __restrict__ b,
                                 size_t total)
{
    size_t i = (size_t)blockIdx.x * blockDim.x + threadIdx.x;
    size_t base = i * 4;
    if (base + 3 < total) {
        float4 v;
        v.x = b[(base + 0) & (F_OUT - 1)];
        v.y = b[(base + 1) & (F_OUT - 1)];
        v.z = b[(base + 2) & (F_OUT - 1)];
        v.w = b[(base + 3) & (F_OUT - 1)];
        *reinterpret_cast<float4*>(out + base) = v;
    } else {
        for (size_t k = base; k < total; k++) out[k] = b[k & (F_OUT - 1)];
    }
}

// ---------------------------------------------------------------------------
// Stage 3: edge scatter. One warp per edge.
// out[row] += val * support[col]   (256 floats, 8 per lane as 2x float4)
// Indices are INT32 (jax default x64-disabled downcasts int64 -> int32).
// ---------------------------------------------------------------------------
__global__ void __launch_bounds__(512) edge_scatter_kernel(
    const int* __restrict__ rows,
    const int* __restrict__ cols,
    const float* __restrict__ vals,
    const float* __restrict__ sup,
    float* __restrict__ out,
    int E)
{
    int warp = (int)(((size_t)blockIdx.x * blockDim.x + threadIdx.x) >> 5);
    int lane = threadIdx.x & 31;
    if (warp >= E) return;

    int r = rows[warp];
    int c = cols[warp];
    float v = vals[warp];

    const float4* s = reinterpret_cast<const float4*>(sup + (size_t)c * F_OUT);
    float* o = out + (size_t)r * F_OUT;

    float4 sv0 = s[lane];
    float4 sv1 = s[lane + 32];

    int f0 = lane * 4;
    atomicAdd(o + f0 + 0, v * sv0.x);
    atomicAdd(o + f0 + 1, v * sv0.y);
    atomicAdd(o + f0 + 2, v * sv0.z);
    atomicAdd(o + f0 + 3, v * sv0.w);

    int f1 = (lane + 32) * 4;
    atomicAdd(o + f1 + 0, v * sv1.x);
    atomicAdd(o + f1 + 1, v * sv1.y);
    atomicAdd(o + f1 + 2, v * sv1.z);
    atomicAdd(o + f1 + 3, v * sv1.w);
}

// ---------------------------------------------------------------------------
extern "C" void kernel_launch(void* const* d_in, const int* in_sizes, int n_in,
                              void* d_out, int out_size)
{
    const float* x     = (const float*)d_in[0];   // [N_NODES, F_IN]
    const int*   erows = (const int*)d_in[1];     // [E]  (int32!)
    const int*   ecols = (const int*)d_in[2];     // [E]  (int32!)
    const float* evals = (const float*)d_in[3];   // [E]
    const float* w     = (const float*)d_in[4];   // [F_IN, F_OUT]
    const float* b     = (const float*)d_in[5];   // [F_OUT]
    float* out = (float*)d_out;

    const int M = in_sizes[0] / F_IN;     // 100000
    const int E = in_sizes[1];            // 3200000

    float* sup = nullptr;
    cudaGetSymbolAddress((void**)&sup, g_support);

    // Stage 1: GEMM
    {
        dim3 grid(F_OUT / BN, (M + BM - 1) / BM);
        gemm_kernel<<<grid, 256>>>(x, w, sup, M);
    }

    // Stage 2: bias init
    {
        size_t total = (size_t)M * F_OUT;
        size_t nth = (total + 3) / 4;
        int threads = 256;
        int blocks = (int)((nth + threads - 1) / threads);
        bias_init_kernel<<<blocks, threads>>>(out, b, total);
    }

    // Stage 3: edge scatter (16 warps / block)
    {
        int warpsPerBlock = 16;
        int blocks = (E + warpsPerBlock - 1) / warpsPerBlock;
        edge_scatter_kernel<<<blocks, 512>>>(erows, ecols, evals, sup, out, E);
    }
}

// round 4
// speedup vs baseline: 2.9326x; 2.9326x over previous
#include <cuda_runtime.h>
#include <cuda_bf16.h>

#define N_NODES 100000
#define F_IN 256
#define F_OUT 256
#define MAX_E 3200000

// ---- device scratch (allocation rules: __device__ globals only) ----
__device__ float g_support[(size_t)N_NODES * F_OUT];   // 102.4 MB
__device__ int   g_scols[MAX_E];                       // sorted-by-row cols
__device__ float g_svals[MAX_E];                       // sorted-by-row vals
__device__ int   g_counts[N_NODES];
__device__ int   g_offsets[N_NODES + 1];
__device__ int   g_cursor[N_NODES];

// ---------------------------------------------------------------------------
// Stage 1: SGEMM  C[M,256] = A[M,256] @ B[256,256]
// 128x128 tile, BK=8, 256 threads, 8x8 micro-tile, float4 global loads.
// ---------------------------------------------------------------------------
#define BM 128
#define BN 128
#define BK 8

__global__ void __launch_bounds__(256) gemm_kernel(
    const float* __restrict__ A,
    const float* __restrict__ B,
    float* __restrict__ C,
    int M)
{
    __shared__ float As[BK][BM];   // transposed A tile
    __shared__ float Bs[BK][BN];

    const int tid = threadIdx.x;
    const int tx = tid & 15;            // 0..15 -> 8 cols each
    const int ty = tid >> 4;            // 0..15 -> 8 rows each
    const int blockRow = blockIdx.y * BM;
    const int blockCol = blockIdx.x * BN;

    // A-load mapping: 128 rows x 8 k -> thread t loads row t/2, k-chunk (t&1)*4
    const int a_row = tid >> 1;
    const int a_k   = (tid & 1) * 4;
    // B-load mapping: 8 k x 128 n -> thread t loads k t/32, n-chunk (t&31)*4
    const int b_k = tid >> 5;
    const int b_n = (tid & 31) * 4;

    float acc[8][8];
#pragma unroll
    for (int i = 0; i < 8; i++)
#pragma unroll
        for (int j = 0; j < 8; j++) acc[i][j] = 0.0f;

    for (int k0 = 0; k0 < F_IN; k0 += BK) {
        // load A tile (transposed store)
        {
            int gr = blockRow + a_row;
            float4 a4 = make_float4(0.f, 0.f, 0.f, 0.f);
            if (gr < M)
                a4 = *reinterpret_cast<const float4*>(A + (size_t)gr * F_IN + k0 + a_k);
            As[a_k + 0][a_row] = a4.x;
            As[a_k + 1][a_row] = a4.y;
            As[a_k + 2][a_row] = a4.z;
            As[a_k + 3][a_row] = a4.w;
        }
        // load B tile
        {
            float4 b4 = *reinterpret_cast<const float4*>(
                B + (size_t)(k0 + b_k) * F_OUT + blockCol + b_n);
            *reinterpret_cast<float4*>(&Bs[b_k][b_n]) = b4;
        }
        __syncthreads();

#pragma unroll
        for (int k = 0; k < BK; k++) {
            float4 ra0 = *reinterpret_cast<const float4*>(&As[k][ty * 8]);
            float4 ra1 = *reinterpret_cast<const float4*>(&As[k][ty * 8 + 4]);
            float4 rb0 = *reinterpret_cast<const float4*>(&Bs[k][tx * 8]);
            float4 rb1 = *reinterpret_cast<const float4*>(&Bs[k][tx * 8 + 4]);
            float ra[8] = {ra0.x, ra0.y, ra0.z, ra0.w, ra1.x, ra1.y, ra1.z, ra1.w};
            float rb[8] = {rb0.x, rb0.y, rb0.z, rb0.w, rb1.x, rb1.y, rb1.z, rb1.w};
#pragma unroll
            for (int i = 0; i < 8; i++)
#pragma unroll
                for (int j = 0; j < 8; j++)
                    acc[i][j] = fmaf(ra[i], rb[j], acc[i][j]);
        }
        __syncthreads();
    }

#pragma unroll
    for (int i = 0; i < 8; i++) {
        int gr = blockRow + ty * 8 + i;
        if (gr < M) {
            float* crow = C + (size_t)gr * F_OUT + blockCol + tx * 8;
            *reinterpret_cast<float4*>(crow)     = make_float4(acc[i][0], acc[i][1], acc[i][2], acc[i][3]);
            *reinterpret_cast<float4*>(crow + 4) = make_float4(acc[i][4], acc[i][5], acc[i][6], acc[i][7]);
        }
    }
}

// ---------------------------------------------------------------------------
// Counting sort of edges by row
// ---------------------------------------------------------------------------
__global__ void zero_counts_kernel(int* __restrict__ counts, int n)
{
    int i = blockIdx.x * blockDim.x + threadIdx.x;
    if (i < n) counts[i] = 0;
}

__global__ void hist_kernel(const int* __restrict__ rows, int* __restrict__ counts, int E)
{
    int i = blockIdx.x * blockDim.x + threadIdx.x;
    int stride = gridDim.x * blockDim.x;
    for (; i < E; i += stride) atomicAdd(&counts[rows[i]], 1);
}

// single-block exclusive scan (n = 100000, 1024 threads, carry across chunks)
__global__ void scan_kernel(const int* __restrict__ counts,
                            int* __restrict__ offsets,
                            int* __restrict__ cursor, int n)
{
    __shared__ int sdata[1024];
    __shared__ int s_carry;
    int tid = threadIdx.x;
    if (tid == 0) s_carry = 0;
    __syncthreads();

    for (int base = 0; base < n; base += 1024) {
        int i = base + tid;
        int x = (i < n) ? counts[i] : 0;
        sdata[tid] = x;
        __syncthreads();
#pragma unroll
        for (int off = 1; off < 1024; off <<= 1) {
            int t = (tid >= off) ? sdata[tid - off] : 0;
            __syncthreads();
            sdata[tid] += t;
            __syncthreads();
        }
        int incl = sdata[tid];
        int excl = s_carry + incl - x;
        if (i < n) { offsets[i] = excl; cursor[i] = excl; }
        __syncthreads();
        if (tid == 1023) s_carry += sdata[1023];
        __syncthreads();
    }
    if (tid == 0) offsets[n] = s_carry;
}

__global__ void scatter_kernel(const int* __restrict__ rows,
                               const int* __restrict__ cols,
                               const float* __restrict__ vals,
                               int* __restrict__ cursor,
                               int* __restrict__ scols,
                               float* __restrict__ svals, int E)
{
    int i = blockIdx.x * blockDim.x + threadIdx.x;
    int stride = gridDim.x * blockDim.x;
    for (; i < E; i += stride) {
        int r = rows[i];
        int pos = atomicAdd(&cursor[r], 1);
        scols[pos] = cols[i];
        svals[pos] = vals[i];
    }
}

// ---------------------------------------------------------------------------
// Stage 3: warp-per-node segmented reduction, no atomics.
// out[node] = bias + sum_e val[e] * support[col[e]]
// ---------------------------------------------------------------------------
__device__ __forceinline__ void fma4(float4& a, float v, const float4& x)
{
    a.x = fmaf(v, x.x, a.x);
    a.y = fmaf(v, x.y, a.y);
    a.z = fmaf(v, x.z, a.z);
    a.w = fmaf(v, x.w, a.w);
}

__global__ void __launch_bounds__(256) gather_reduce_kernel(
    const int* __restrict__ offsets,
    const int* __restrict__ scols,
    const float* __restrict__ svals,
    const float* __restrict__ sup,
    const float* __restrict__ bias,
    float* __restrict__ out,
    int M)
{
    int warp = (int)((blockIdx.x * blockDim.x + threadIdx.x) >> 5);
    int lane = threadIdx.x & 31;
    if (warp >= M) return;

    int start = offsets[warp];
    int end   = offsets[warp + 1];

    float4 a0 = make_float4(0.f, 0.f, 0.f, 0.f);
    float4 a1 = make_float4(0.f, 0.f, 0.f, 0.f);

    int e = start;
    for (; e + 1 < end; e += 2) {
        int   c0 = __ldcs(&scols[e]);
        int   c1 = __ldcs(&scols[e + 1]);
        float v0 = __ldcs(&svals[e]);
        float v1 = __ldcs(&svals[e + 1]);
        const float4* s0 = reinterpret_cast<const float4*>(sup + (size_t)c0 * F_OUT);
        const float4* s1 = reinterpret_cast<const float4*>(sup + (size_t)c1 * F_OUT);
        float4 x00 = s0[lane];
        float4 x01 = s0[lane + 32];
        float4 x10 = s1[lane];
        float4 x11 = s1[lane + 32];
        fma4(a0, v0, x00);
        fma4(a1, v0, x01);
        fma4(a0, v1, x10);
        fma4(a1, v1, x11);
    }
    if (e < end) {
        int   c = __ldcs(&scols[e]);
        float v = __ldcs(&svals[e]);
        const float4* s = reinterpret_cast<const float4*>(sup + (size_t)c * F_OUT);
        fma4(a0, v, s[lane]);
        fma4(a1, v, s[lane + 32]);
    }

    const float4* b4 = reinterpret_cast<const float4*>(bias);
    float4 bb0 = b4[lane];
    float4 bb1 = b4[lane + 32];
    a0.x += bb0.x; a0.y += bb0.y; a0.z += bb0.z; a0.w += bb0.w;
    a1.x += bb1.x; a1.y += bb1.y; a1.z += bb1.z; a1.w += bb1.w;

    float4* orow = reinterpret_cast<float4*>(out + (size_t)warp * F_OUT);
    __stcs(&orow[lane], a0);
    __stcs(&orow[lane + 32], a1);
}

// ---------------------------------------------------------------------------
extern "C" void kernel_launch(void* const* d_in, const int* in_sizes, int n_in,
                              void* d_out, int out_size)
{
    const float* x     = (const float*)d_in[0];   // [N_NODES, F_IN]
    const int*   erows = (const int*)d_in[1];     // [E] int32
    const int*   ecols = (const int*)d_in[2];     // [E] int32
    const float* evals = (const float*)d_in[3];   // [E]
    const float* w     = (const float*)d_in[4];   // [F_IN, F_OUT]
    const float* b     = (const float*)d_in[5];   // [F_OUT]
    float* out = (float*)d_out;

    const int M = in_sizes[0] / F_IN;     // 100000
    const int E = in_sizes[1];            // 3200000

    float *sup, *svals;
    int *scols, *counts, *offsets, *cursor;
    cudaGetSymbolAddress((void**)&sup,     g_support);
    cudaGetSymbolAddress((void**)&scols,   g_scols);
    cudaGetSymbolAddress((void**)&svals,   g_svals);
    cudaGetSymbolAddress((void**)&counts,  g_counts);
    cudaGetSymbolAddress((void**)&offsets, g_offsets);
    cudaGetSymbolAddress((void**)&cursor,  g_cursor);

    // Stage 1: GEMM
    {
        dim3 grid(F_OUT / BN, (M + BM - 1) / BM);
        gemm_kernel<<<grid, 256>>>(x, w, sup, M);
    }

    // Stage 2: counting sort of edges by row
    zero_counts_kernel<<<(M + 255) / 256, 256>>>(counts, M);
    hist_kernel<<<1184, 256>>>(erows, counts, E);            // 148 SMs * 8 blocks
    scan_kernel<<<1, 1024>>>(counts, offsets, cursor, M);
    scatter_kernel<<<1184, 256>>>(erows, ecols, evals, cursor, scols, svals, E);

    // Stage 3: warp-per-node reduction (8 warps / block)
    {
        int warpsPerBlock = 8;
        int blocks = (M + warpsPerBlock - 1) / warpsPerBlock;
        gather_reduce_kernel<<<blocks, 256>>>(offsets, scols, svals, sup, b, out, M);
    }
}

// round 5
// speedup vs baseline: 3.4573x; 1.1789x over previous
#include <cuda_runtime.h>
#include <cuda_bf16.h>

#define N_NODES 100000
#define F_IN 256
#define F_OUT 256
#define MAX_E 3200000

#define SCAN_CHUNK 1024
#define N_CHUNKS ((N_NODES + SCAN_CHUNK - 1) / SCAN_CHUNK)   // 98

// ---- device scratch (allocation rules: __device__ globals only) ----
__device__ float g_support[(size_t)N_NODES * F_OUT];   // 102.4 MB
__device__ int   g_scols[MAX_E];
__device__ float g_svals[MAX_E];
__device__ int   g_counts[N_NODES];
__device__ int   g_offsets[N_NODES + 1];
__device__ int   g_cursor[N_NODES];
__device__ int   g_blocksums[N_CHUNKS];

// ---------------------------------------------------------------------------
// Stage 1: SGEMM  C[M,256] = A[M,256] @ B[256,256]
// 128x128 tile, BK=8, 256 threads, 8x8 micro-tile, float4 global loads.
// ---------------------------------------------------------------------------
#define BM 128
#define BN 128
#define BK 8

__global__ void __launch_bounds__(256) gemm_kernel(
    const float* __restrict__ A,
    const float* __restrict__ B,
    float* __restrict__ C,
    int M)
{
    __shared__ float As[BK][BM];   // transposed A tile
    __shared__ float Bs[BK][BN];

    const int tid = threadIdx.x;
    const int tx = tid & 15;
    const int ty = tid >> 4;
    const int blockRow = blockIdx.y * BM;
    const int blockCol = blockIdx.x * BN;

    const int a_row = tid >> 1;
    const int a_k   = (tid & 1) * 4;
    const int b_k = tid >> 5;
    const int b_n = (tid & 31) * 4;

    float acc[8][8];
#pragma unroll
    for (int i = 0; i < 8; i++)
#pragma unroll
        for (int j = 0; j < 8; j++) acc[i][j] = 0.0f;

    for (int k0 = 0; k0 < F_IN; k0 += BK) {
        {
            int gr = blockRow + a_row;
            float4 a4 = make_float4(0.f, 0.f, 0.f, 0.f);
            if (gr < M)
                a4 = *reinterpret_cast<const float4*>(A + (size_t)gr * F_IN + k0 + a_k);
            As[a_k + 0][a_row] = a4.x;
            As[a_k + 1][a_row] = a4.y;
            As[a_k + 2][a_row] = a4.z;
            As[a_k + 3][a_row] = a4.w;
        }
        {
            float4 b4 = *reinterpret_cast<const float4*>(
                B + (size_t)(k0 + b_k) * F_OUT + blockCol + b_n);
            *reinterpret_cast<float4*>(&Bs[b_k][b_n]) = b4;
        }
        __syncthreads();

#pragma unroll
        for (int k = 0; k < BK; k++) {
            float4 ra0 = *reinterpret_cast<const float4*>(&As[k][ty * 8]);
            float4 ra1 = *reinterpret_cast<const float4*>(&As[k][ty * 8 + 4]);
            float4 rb0 = *reinterpret_cast<const float4*>(&Bs[k][tx * 8]);
            float4 rb1 = *reinterpret_cast<const float4*>(&Bs[k][tx * 8 + 4]);
            float ra[8] = {ra0.x, ra0.y, ra0.z, ra0.w, ra1.x, ra1.y, ra1.z, ra1.w};
            float rb[8] = {rb0.x, rb0.y, rb0.z, rb0.w, rb1.x, rb1.y, rb1.z, rb1.w};
#pragma unroll
            for (int i = 0; i < 8; i++)
#pragma unroll
                for (int j = 0; j < 8; j++)
                    acc[i][j] = fmaf(ra[i], rb[j], acc[i][j]);
        }
        __syncthreads();
    }

#pragma unroll
    for (int i = 0; i < 8; i++) {
        int gr = blockRow + ty * 8 + i;
        if (gr < M) {
            float* crow = C + (size_t)gr * F_OUT + blockCol + tx * 8;
            *reinterpret_cast<float4*>(crow)     = make_float4(acc[i][0], acc[i][1], acc[i][2], acc[i][3]);
            *reinterpret_cast<float4*>(crow + 4) = make_float4(acc[i][4], acc[i][5], acc[i][6], acc[i][7]);
        }
    }
}

// ---------------------------------------------------------------------------
// Counting sort of edges by row
// ---------------------------------------------------------------------------
__global__ void zero_counts_kernel(int* __restrict__ counts, int n)
{
    int i = blockIdx.x * blockDim.x + threadIdx.x;
    if (i < n) counts[i] = 0;
}

__global__ void hist_kernel(const int* __restrict__ rows, int* __restrict__ counts, int E)
{
    int i = blockIdx.x * blockDim.x + threadIdx.x;
    int stride = gridDim.x * blockDim.x;
    for (; i < E; i += stride) atomicAdd(&counts[__ldcs(&rows[i])], 1);
}

// ---- parallel 3-pass scan ----
// Pass 1: per-chunk exclusive scan (within chunk), emit chunk total.
__global__ void __launch_bounds__(1024) scan_pass1(
    const int* __restrict__ counts,
    int* __restrict__ offsets,          // holds local-exclusive for now
    int* __restrict__ blocksums, int n)
{
    __shared__ int sdata[SCAN_CHUNK];
    int tid = threadIdx.x;
    int i = blockIdx.x * SCAN_CHUNK + tid;
    int x = (i < n) ? counts[i] : 0;
    sdata[tid] = x;
    __syncthreads();
#pragma unroll
    for (int off = 1; off < SCAN_CHUNK; off <<= 1) {
        int t = (tid >= off) ? sdata[tid - off] : 0;
        __syncthreads();
        sdata[tid] += t;
        __syncthreads();
    }
    if (i < n) offsets[i] = sdata[tid] - x;   // local exclusive
    if (tid == SCAN_CHUNK - 1) blocksums[blockIdx.x] = sdata[tid];
}

// Pass 2: single small block scans the chunk totals (exclusive, in-place).
__global__ void scan_pass2(int* __restrict__ blocksums, int* __restrict__ total_out, int nchunks)
{
    __shared__ int sdata[128];
    int tid = threadIdx.x;
    int x = (tid < nchunks) ? blocksums[tid] : 0;
    sdata[tid] = x;
    __syncthreads();
#pragma unroll
    for (int off = 1; off < 128; off <<= 1) {
        int t = (tid >= off) ? sdata[tid - off] : 0;
        __syncthreads();
        sdata[tid] += t;
        __syncthreads();
    }
    if (tid < nchunks) blocksums[tid] = sdata[tid] - x;  // exclusive
    if (tid == 127) *total_out = sdata[127];             // grand total -> offsets[n]
}

// Pass 3: add chunk carry, finalize offsets + cursor.
__global__ void __launch_bounds__(1024) scan_pass3(
    int* __restrict__ offsets,
    int* __restrict__ cursor,
    const int* __restrict__ blocksums, int n)
{
    int i = blockIdx.x * SCAN_CHUNK + threadIdx.x;
    if (i < n) {
        int v = offsets[i] + blocksums[blockIdx.x];
        offsets[i] = v;
        cursor[i] = v;
    }
}

__global__ void scatter_kernel(const int* __restrict__ rows,
                               const int* __restrict__ cols,
                               const float* __restrict__ vals,
                               int* __restrict__ cursor,
                               int* __restrict__ scols,
                               float* __restrict__ svals, int E)
{
    int i = blockIdx.x * blockDim.x + threadIdx.x;
    int stride = gridDim.x * blockDim.x;
    for (; i < E; i += stride) {
        int r = __ldcs(&rows[i]);
        int pos = atomicAdd(&cursor[r], 1);
        scols[pos] = __ldcs(&cols[i]);
        svals[pos] = __ldcs(&vals[i]);
    }
}

// ---------------------------------------------------------------------------
// Stage 3: warp-per-node segmented reduction, no atomics.
// ---------------------------------------------------------------------------
__device__ __forceinline__ void fma4(float4& a, float v, const float4& x)
{
    a.x = fmaf(v, x.x, a.x);
    a.y = fmaf(v, x.y, a.y);
    a.z = fmaf(v, x.z, a.z);
    a.w = fmaf(v, x.w, a.w);
}

__global__ void __launch_bounds__(256) gather_reduce_kernel(
    const int* __restrict__ offsets,
    const int* __restrict__ scols,
    const float* __restrict__ svals,
    const float* __restrict__ sup,
    const float* __restrict__ bias,
    float* __restrict__ out,
    int M)
{
    int warp = (int)((blockIdx.x * blockDim.x + threadIdx.x) >> 5);
    int lane = threadIdx.x & 31;
    if (warp >= M) return;

    int start = offsets[warp];
    int end   = offsets[warp + 1];

    float4 a0 = make_float4(0.f, 0.f, 0.f, 0.f);
    float4 a1 = make_float4(0.f, 0.f, 0.f, 0.f);

    int e = start;
    for (; e + 1 < end; e += 2) {
        int   c0 = __ldcs(&scols[e]);
        int   c1 = __ldcs(&scols[e + 1]);
        float v0 = __ldcs(&svals[e]);
        float v1 = __ldcs(&svals[e + 1]);
        const float4* s0 = reinterpret_cast<const float4*>(sup + (size_t)c0 * F_OUT);
        const float4* s1 = reinterpret_cast<const float4*>(sup + (size_t)c1 * F_OUT);
        float4 x00 = s0[lane];
        float4 x01 = s0[lane + 32];
        float4 x10 = s1[lane];
        float4 x11 = s1[lane + 32];
        fma4(a0, v0, x00);
        fma4(a1, v0, x01);
        fma4(a0, v1, x10);
        fma4(a1, v1, x11);
    }
    if (e < end) {
        int   c = __ldcs(&scols[e]);
        float v = __ldcs(&svals[e]);
        const float4* s = reinterpret_cast<const float4*>(sup + (size_t)c * F_OUT);
        fma4(a0, v, s[lane]);
        fma4(a1, v, s[lane + 32]);
    }

    const float4* b4 = reinterpret_cast<const float4*>(bias);
    float4 bb0 = b4[lane];
    float4 bb1 = b4[lane + 32];
    a0.x += bb0.x; a0.y += bb0.y; a0.z += bb0.z; a0.w += bb0.w;
    a1.x += bb1.x; a1.y += bb1.y; a1.z += bb1.z; a1.w += bb1.w;

    float4* orow = reinterpret_cast<float4*>(out + (size_t)warp * F_OUT);
    __stcs(&orow[lane], a0);
    __stcs(&orow[lane + 32], a1);
}

// ---------------------------------------------------------------------------
extern "C" void kernel_launch(void* const* d_in, const int* in_sizes, int n_in,
                              void* d_out, int out_size)
{
    const float* x     = (const float*)d_in[0];
    const int*   erows = (const int*)d_in[1];
    const int*   ecols = (const int*)d_in[2];
    const float* evals = (const float*)d_in[3];
    const float* w     = (const float*)d_in[4];
    const float* b     = (const float*)d_in[5];
    float* out = (float*)d_out;

    const int M = in_sizes[0] / F_IN;     // 100000
    const int E = in_sizes[1];            // 3200000

    float *sup, *svals;
    int *scols, *counts, *offsets, *cursor, *blocksums;
    cudaGetSymbolAddress((void**)&sup,       g_support);
    cudaGetSymbolAddress((void**)&scols,     g_scols);
    cudaGetSymbolAddress((void**)&svals,     g_svals);
    cudaGetSymbolAddress((void**)&counts,    g_counts);
    cudaGetSymbolAddress((void**)&offsets,   g_offsets);
    cudaGetSymbolAddress((void**)&cursor,    g_cursor);
    cudaGetSymbolAddress((void**)&blocksums, g_blocksums);

    // Stage 1: GEMM
    {
        dim3 grid(F_OUT / BN, (M + BM - 1) / BM);
        gemm_kernel<<<grid, 256>>>(x, w, sup, M);
    }

    // Stage 2: counting sort of edges by row (parallel scan)
    const int nchunks = (M + SCAN_CHUNK - 1) / SCAN_CHUNK;
    zero_counts_kernel<<<(M + 255) / 256, 256>>>(counts, M);
    hist_kernel<<<1184, 256>>>(erows, counts, E);
    scan_pass1<<<nchunks, SCAN_CHUNK>>>(counts, offsets, blocksums, M);
    scan_pass2<<<1, 128>>>(blocksums, offsets + M, nchunks);
    scan_pass3<<<nchunks, SCAN_CHUNK>>>(offsets, cursor, blocksums, M);
    scatter_kernel<<<1184, 256>>>(erows, ecols, evals, cursor, scols, svals, E);

    // Stage 3: warp-per-node reduction
    {
        int warpsPerBlock = 8;
        int blocks = (M + warpsPerBlock - 1) / warpsPerBlock;
        gather_reduce_kernel<<<blocks, 256>>>(offsets, scols, svals, sup, b, out, M);
    }
}

// round 6
// speedup vs baseline: 4.4888x; 1.2984x over previous
#include <cuda_runtime.h>
#include <cuda_fp16.h>
#include <cuda_bf16.h>

#define N_NODES 100000
#define F_IN 256
#define F_OUT 256
#define MAX_E 3200000

#define SCAN_CHUNK 1024
#define N_CHUNKS ((N_NODES + SCAN_CHUNK - 1) / SCAN_CHUNK)   // 98

// ---- device scratch (allocation rules: __device__ globals only) ----
__device__ __half g_support_h[(size_t)N_NODES * F_OUT];  // 51.2 MB (fp16)
__device__ int2   g_edata[MAX_E];                        // packed (col, val)
__device__ int    g_counts[N_NODES];
__device__ int    g_offsets[N_NODES + 1];
__device__ int    g_cursor[N_NODES];
__device__ int    g_blocksums[N_CHUNKS];

// ---------------------------------------------------------------------------
// Stage 1: SGEMM  C[M,256] = A[M,256] @ B[256,256], fp32 accum, fp16 store.
// 128x128 tile, BK=8, 256 threads, 8x8 micro-tile, float4 global loads.
// ---------------------------------------------------------------------------
#define BM 128
#define BN 128
#define BK 8

__global__ void __launch_bounds__(256) gemm_kernel(
    const float* __restrict__ A,
    const float* __restrict__ B,
    __half* __restrict__ C,
    int M)
{
    __shared__ float As[BK][BM];   // transposed A tile
    __shared__ float Bs[BK][BN];

    const int tid = threadIdx.x;
    const int tx = tid & 15;
    const int ty = tid >> 4;
    const int blockRow = blockIdx.y * BM;
    const int blockCol = blockIdx.x * BN;

    const int a_row = tid >> 1;
    const int a_k   = (tid & 1) * 4;
    const int b_k = tid >> 5;
    const int b_n = (tid & 31) * 4;

    float acc[8][8];
#pragma unroll
    for (int i = 0; i < 8; i++)
#pragma unroll
        for (int j = 0; j < 8; j++) acc[i][j] = 0.0f;

    for (int k0 = 0; k0 < F_IN; k0 += BK) {
        {
            int gr = blockRow + a_row;
            float4 a4 = make_float4(0.f, 0.f, 0.f, 0.f);
            if (gr < M)
                a4 = *reinterpret_cast<const float4*>(A + (size_t)gr * F_IN + k0 + a_k);
            As[a_k + 0][a_row] = a4.x;
            As[a_k + 1][a_row] = a4.y;
            As[a_k + 2][a_row] = a4.z;
            As[a_k + 3][a_row] = a4.w;
        }
        {
            float4 b4 = *reinterpret_cast<const float4*>(
                B + (size_t)(k0 + b_k) * F_OUT + blockCol + b_n);
            *reinterpret_cast<float4*>(&Bs[b_k][b_n]) = b4;
        }
        __syncthreads();

#pragma unroll
        for (int k = 0; k < BK; k++) {
            float4 ra0 = *reinterpret_cast<const float4*>(&As[k][ty * 8]);
            float4 ra1 = *reinterpret_cast<const float4*>(&As[k][ty * 8 + 4]);
            float4 rb0 = *reinterpret_cast<const float4*>(&Bs[k][tx * 8]);
            float4 rb1 = *reinterpret_cast<const float4*>(&Bs[k][tx * 8 + 4]);
            float ra[8] = {ra0.x, ra0.y, ra0.z, ra0.w, ra1.x, ra1.y, ra1.z, ra1.w};
            float rb[8] = {rb0.x, rb0.y, rb0.z, rb0.w, rb1.x, rb1.y, rb1.z, rb1.w};
#pragma unroll
            for (int i = 0; i < 8; i++)
#pragma unroll
                for (int j = 0; j < 8; j++)
                    acc[i][j] = fmaf(ra[i], rb[j], acc[i][j]);
        }
        __syncthreads();
    }

    // Epilogue: convert to fp16, one 16B store per row (8 halves).
#pragma unroll
    for (int i = 0; i < 8; i++) {
        int gr = blockRow + ty * 8 + i;
        if (gr < M) {
            __half2 h[4];
#pragma unroll
            for (int j = 0; j < 4; j++)
                h[j] = __floats2half2_rn(acc[i][2 * j], acc[i][2 * j + 1]);
            uint4* crow = reinterpret_cast<uint4*>(
                C + (size_t)gr * F_OUT + blockCol + tx * 8);
            *crow = *reinterpret_cast<uint4*>(h);
        }
    }
}

// ---------------------------------------------------------------------------
// Counting sort of edges by row
// ---------------------------------------------------------------------------
__global__ void zero_counts_kernel(int* __restrict__ counts, int n)
{
    int i = blockIdx.x * blockDim.x + threadIdx.x;
    if (i < n) counts[i] = 0;
}

__global__ void hist_kernel(const int* __restrict__ rows, int* __restrict__ counts, int E)
{
    int i = blockIdx.x * blockDim.x + threadIdx.x;
    int stride = gridDim.x * blockDim.x;
    for (; i < E; i += stride) atomicAdd(&counts[__ldcs(&rows[i])], 1);
}

__global__ void __launch_bounds__(1024) scan_pass1(
    const int* __restrict__ counts,
    int* __restrict__ offsets,
    int* __restrict__ blocksums, int n)
{
    __shared__ int sdata[SCAN_CHUNK];
    int tid = threadIdx.x;
    int i = blockIdx.x * SCAN_CHUNK + tid;
    int x = (i < n) ? counts[i] : 0;
    sdata[tid] = x;
    __syncthreads();
#pragma unroll
    for (int off = 1; off < SCAN_CHUNK; off <<= 1) {
        int t = (tid >= off) ? sdata[tid - off] : 0;
        __syncthreads();
        sdata[tid] += t;
        __syncthreads();
    }
    if (i < n) offsets[i] = sdata[tid] - x;   // local exclusive
    if (tid == SCAN_CHUNK - 1) blocksums[blockIdx.x] = sdata[tid];
}

__global__ void scan_pass2(int* __restrict__ blocksums, int* __restrict__ total_out, int nchunks)
{
    __shared__ int sdata[128];
    int tid = threadIdx.x;
    int x = (tid < nchunks) ? blocksums[tid] : 0;
    sdata[tid] = x;
    __syncthreads();
#pragma unroll
    for (int off = 1; off < 128; off <<= 1) {
        int t = (tid >= off) ? sdata[tid - off] : 0;
        __syncthreads();
        sdata[tid] += t;
        __syncthreads();
    }
    if (tid < nchunks) blocksums[tid] = sdata[tid] - x;  // exclusive
    if (tid == 127) *total_out = sdata[127];
}

__global__ void __launch_bounds__(1024) scan_pass3(
    int* __restrict__ offsets,
    int* __restrict__ cursor,
    const int* __restrict__ blocksums, int n)
{
    int i = blockIdx.x * SCAN_CHUNK + threadIdx.x;
    if (i < n) {
        int v = offsets[i] + blocksums[blockIdx.x];
        offsets[i] = v;
        cursor[i] = v;
    }
}

__global__ void scatter_kernel(const int* __restrict__ rows,
                               const int* __restrict__ cols,
                               const float* __restrict__ vals,
                               int* __restrict__ cursor,
                               int2* __restrict__ edata, int E)
{
    int i = blockIdx.x * blockDim.x + threadIdx.x;
    int stride = gridDim.x * blockDim.x;
    for (; i < E; i += stride) {
        int r = __ldcs(&rows[i]);
        int pos = atomicAdd(&cursor[r], 1);
        edata[pos] = make_int2(__ldcs(&cols[i]), __float_as_int(__ldcs(&vals[i])));
    }
}

// ---------------------------------------------------------------------------
// Stage 3: warp-per-node segmented reduction (fp16 gather, fp32 accum).
// Each lane covers features [lane*8, lane*8+8) via ONE uint4 load per edge.
// ---------------------------------------------------------------------------
__global__ void __launch_bounds__(256) gather_reduce_kernel(
    const int* __restrict__ offsets,
    const int2* __restrict__ edata,
    const __half* __restrict__ sup,
    const float* __restrict__ bias,
    float* __restrict__ out,
    int M)
{
    int warp = (int)((blockIdx.x * blockDim.x + threadIdx.x) >> 5);
    int lane = threadIdx.x & 31;
    if (warp >= M) return;

    int start = offsets[warp];
    int end   = offsets[warp + 1];

    float acc[8];
#pragma unroll
    for (int j = 0; j < 8; j++) acc[j] = 0.0f;

    int e = start;
    for (; e + 1 < end; e += 2) {
        int2 ed0 = __ldcs(&edata[e]);
        int2 ed1 = __ldcs(&edata[e + 1]);
        float v0 = __int_as_float(ed0.y);
        float v1 = __int_as_float(ed1.y);
        uint4 p0 = reinterpret_cast<const uint4*>(sup + (size_t)ed0.x * F_OUT)[lane];
        uint4 p1 = reinterpret_cast<const uint4*>(sup + (size_t)ed1.x * F_OUT)[lane];
        const __half2* h0 = reinterpret_cast<const __half2*>(&p0);
        const __half2* h1 = reinterpret_cast<const __half2*>(&p1);
#pragma unroll
        for (int j = 0; j < 4; j++) {
            float2 f0 = __half22float2(h0[j]);
            float2 f1 = __half22float2(h1[j]);
            acc[2 * j]     = fmaf(v0, f0.x, acc[2 * j]);
            acc[2 * j + 1] = fmaf(v0, f0.y, acc[2 * j + 1]);
            acc[2 * j]     = fmaf(v1, f1.x, acc[2 * j]);
            acc[2 * j + 1] = fmaf(v1, f1.y, acc[2 * j + 1]);
        }
    }
    if (e < end) {
        int2 ed = __ldcs(&edata[e]);
        float v = __int_as_float(ed.y);
        uint4 p = reinterpret_cast<const uint4*>(sup + (size_t)ed.x * F_OUT)[lane];
        const __half2* h = reinterpret_cast<const __half2*>(&p);
#pragma unroll
        for (int j = 0; j < 4; j++) {
            float2 f = __half22float2(h[j]);
            acc[2 * j]     = fmaf(v, f.x, acc[2 * j]);
            acc[2 * j + 1] = fmaf(v, f.y, acc[2 * j + 1]);
        }
    }

    // bias + store: features [lane*8, lane*8+8)
    const float4* b4 = reinterpret_cast<const float4*>(bias) + lane * 2;
    float4 bb0 = b4[0];
    float4 bb1 = b4[1];
    float4 o0 = make_float4(acc[0] + bb0.x, acc[1] + bb0.y, acc[2] + bb0.z, acc[3] + bb0.w);
    float4 o1 = make_float4(acc[4] + bb1.x, acc[5] + bb1.y, acc[6] + bb1.z, acc[7] + bb1.w);

    float4* orow = reinterpret_cast<float4*>(out + (size_t)warp * F_OUT) + lane * 2;
    __stcs(&orow[0], o0);
    __stcs(&orow[1], o1);
}

// ---------------------------------------------------------------------------
extern "C" void kernel_launch(void* const* d_in, const int* in_sizes, int n_in,
                              void* d_out, int out_size)
{
    const float* x     = (const float*)d_in[0];
    const int*   erows = (const int*)d_in[1];
    const int*   ecols = (const int*)d_in[2];
    const float* evals = (const float*)d_in[3];
    const float* w     = (const float*)d_in[4];
    const float* b     = (const float*)d_in[5];
    float* out = (float*)d_out;

    const int M = in_sizes[0] / F_IN;     // 100000
    const int E = in_sizes[1];            // 3200000

    __half* sup;
    int2* edata;
    int *counts, *offsets, *cursor, *blocksums;
    cudaGetSymbolAddress((void**)&sup,       g_support_h);
    cudaGetSymbolAddress((void**)&edata,     g_edata);
    cudaGetSymbolAddress((void**)&counts,    g_counts);
    cudaGetSymbolAddress((void**)&offsets,   g_offsets);
    cudaGetSymbolAddress((void**)&cursor,    g_cursor);
    cudaGetSymbolAddress((void**)&blocksums, g_blocksums);

    // Stage 1: GEMM (fp32 accum -> fp16 support)
    {
        dim3 grid(F_OUT / BN, (M + BM - 1) / BM);
        gemm_kernel<<<grid, 256>>>(x, w, sup, M);
    }

    // Stage 2: counting sort of edges by row
    const int nchunks = (M + SCAN_CHUNK - 1) / SCAN_CHUNK;
    zero_counts_kernel<<<(M + 255) / 256, 256>>>(counts, M);
    hist_kernel<<<1184, 256>>>(erows, counts, E);
    scan_pass1<<<nchunks, SCAN_CHUNK>>>(counts, offsets, blocksums, M);
    scan_pass2<<<1, 128>>>(blocksums, offsets + M, nchunks);
    scan_pass3<<<nchunks, SCAN_CHUNK>>>(offsets, cursor, blocksums, M);
    scatter_kernel<<<1184, 256>>>(erows, ecols, evals, cursor, edata, E);

    // Stage 3: warp-per-node reduction
    {
        int warpsPerBlock = 8;
        int blocks = (M + warpsPerBlock - 1) / warpsPerBlock;
        gather_reduce_kernel<<<blocks, 256>>>(offsets, edata, sup, b, out, M);
    }
}

// round 8
// speedup vs baseline: 7.4928x; 1.6692x over previous
#include <cuda_runtime.h>
#include <cuda_fp16.h>
#include <cuda_bf16.h>
#include <cstdint>

#define N_NODES 100000
#define F_IN 256
#define F_OUT 256
#define MAX_E 3200000

#define SCAN_CHUNK 1024
#define N_CHUNKS ((N_NODES + SCAN_CHUNK - 1) / SCAN_CHUNK)   // 98

// ---- device scratch (allocation rules: __device__ globals only) ----
__device__ __half g_support_h[(size_t)N_NODES * F_OUT];  // 51.2 MB (fp16)
__device__ int2   g_edata[MAX_E];                        // packed (col, val)
__device__ int    g_counts[N_NODES];
__device__ int    g_offsets[N_NODES + 1];
__device__ int    g_cursor[N_NODES];
__device__ int    g_blocksums[N_CHUNKS];

// ---------------------------------------------------------------------------
// Stage 1: TF32 tensor-core GEMM  C[M,256] = A[M,256] @ B[256,256]
// 128x128x32 block tile, 8 warps (each 64x32 = 4x4 m16n8k8 fragments),
// fp32 accum, fp16 store. cvt to tf32 once at SMEM store.
// ---------------------------------------------------------------------------
#define GBM 128
#define GBN 128
#define GBK 32
#define AS_STRIDE 36    // [m][k], bank = 4m+k : conflict-free fragment reads
#define BS_STRIDE 136   // [k][n], bank = 8k+n : conflict-free fragment reads

__device__ __forceinline__ uint32_t f32_to_tf32(float f)
{
    uint32_t u;
    asm volatile("cvt.rna.tf32.f32 %0, %1;" : "=r"(u) : "f"(f));
    return u;
}

__device__ __forceinline__ void mma_tf32(
    float& d0, float& d1, float& d2, float& d3,
    uint32_t a0, uint32_t a1, uint32_t a2, uint32_t a3,
    uint32_t b0, uint32_t b1)
{
    asm volatile(
        "mma.sync.aligned.m16n8k8.row.col.f32.tf32.tf32.f32 "
        "{%0,%1,%2,%3}, {%4,%5,%6,%7}, {%8,%9}, {%0,%1,%2,%3};\n"
        : "+f"(d0), "+f"(d1), "+f"(d2), "+f"(d3)
        : "r"(a0), "r"(a1), "r"(a2), "r"(a3), "r"(b0), "r"(b1));
}

__global__ void __launch_bounds__(256) gemm_tc_kernel(
    const float* __restrict__ A,
    const float* __restrict__ B,
    __half* __restrict__ C,
    int M)
{
    __shared__ uint32_t As[GBM][AS_STRIDE];   // tf32 bits
    __shared__ uint32_t Bs[GBK][BS_STRIDE];   // tf32 bits

    const int tid = threadIdx.x;
    const int lane = tid & 31;
    const int warp = tid >> 5;
    const int warpRow = warp >> 2;            // 0..1 -> m offset *64
    const int warpCol = warp & 3;             // 0..3 -> n offset *32
    const int blockRow = blockIdx.y * GBM;
    const int blockCol = blockIdx.x * GBN;

    const int lq = lane >> 2;                 // lane/4
    const int lr = lane & 3;                  // lane%4

    float d[4][4][4];
#pragma unroll
    for (int mt = 0; mt < 4; mt++)
#pragma unroll
        for (int nt = 0; nt < 4; nt++)
#pragma unroll
            for (int r = 0; r < 4; r++) d[mt][nt][r] = 0.0f;

    for (int k0 = 0; k0 < F_IN; k0 += GBK) {
        // Load A tile: 128x32 floats = 1024 float4, 4 per thread.
#pragma unroll
        for (int i = 0; i < 4; i++) {
            int idx = tid + i * 256;
            int row = idx >> 3;
            int kc = (idx & 7) * 4;
            int gr = blockRow + row;
            float4 a4 = make_float4(0.f, 0.f, 0.f, 0.f);
            if (gr < M)
                a4 = *reinterpret_cast<const float4*>(A + (size_t)gr * F_IN + k0 + kc);
            uint4 t;
            t.x = f32_to_tf32(a4.x);
            t.y = f32_to_tf32(a4.y);
            t.z = f32_to_tf32(a4.z);
            t.w = f32_to_tf32(a4.w);
            *reinterpret_cast<uint4*>(&As[row][kc]) = t;
        }
        // Load B tile: 32x128 floats = 1024 float4, 4 per thread.
#pragma unroll
        for (int i = 0; i < 4; i++) {
            int idx = tid + i * 256;
            int row = idx >> 5;
            int cc = (idx & 31) * 4;
            float4 b4 = *reinterpret_cast<const float4*>(
                B + (size_t)(k0 + row) * F_OUT + blockCol + cc);
            uint4 t;
            t.x = f32_to_tf32(b4.x);
            t.y = f32_to_tf32(b4.y);
            t.z = f32_to_tf32(b4.z);
            t.w = f32_to_tf32(b4.w);
            *reinterpret_cast<uint4*>(&Bs[row][cc]) = t;
        }
        __syncthreads();

#pragma unroll
        for (int kk = 0; kk < GBK; kk += 8) {
            uint32_t af[4][4];
#pragma unroll
            for (int mt = 0; mt < 4; mt++) {
                int r0 = warpRow * 64 + mt * 16 + lq;
                af[mt][0] = As[r0][kk + lr];
                af[mt][1] = As[r0 + 8][kk + lr];
                af[mt][2] = As[r0][kk + lr + 4];
                af[mt][3] = As[r0 + 8][kk + lr + 4];
            }
            uint32_t bf[4][2];
#pragma unroll
            for (int nt = 0; nt < 4; nt++) {
                int n0 = warpCol * 32 + nt * 8 + lq;
                bf[nt][0] = Bs[kk + lr][n0];
                bf[nt][1] = Bs[kk + lr + 4][n0];
            }
#pragma unroll
            for (int mt = 0; mt < 4; mt++)
#pragma unroll
                for (int nt = 0; nt < 4; nt++)
                    mma_tf32(d[mt][nt][0], d[mt][nt][1], d[mt][nt][2], d[mt][nt][3],
                             af[mt][0], af[mt][1], af[mt][2], af[mt][3],
                             bf[nt][0], bf[nt][1]);
        }
        __syncthreads();
    }

    // Epilogue: D layout m16n8 -> (row=lq, col=2*lr) pairs; fp16 __half2 stores.
#pragma unroll
    for (int mt = 0; mt < 4; mt++) {
        int r0 = blockRow + warpRow * 64 + mt * 16 + lq;
        int r1 = r0 + 8;
#pragma unroll
        for (int nt = 0; nt < 4; nt++) {
            int c = blockCol + warpCol * 32 + nt * 8 + 2 * lr;
            if (r0 < M)
                *reinterpret_cast<__half2*>(C + (size_t)r0 * F_OUT + c) =
                    __floats2half2_rn(d[mt][nt][0], d[mt][nt][1]);
            if (r1 < M)
                *reinterpret_cast<__half2*>(C + (size_t)r1 * F_OUT + c) =
                    __floats2half2_rn(d[mt][nt][2], d[mt][nt][3]);
        }
    }
}

// ---------------------------------------------------------------------------
// Counting sort of edges by row
// ---------------------------------------------------------------------------
__global__ void zero_counts_kernel(int* __restrict__ counts, int n)
{
    int i = blockIdx.x * blockDim.x + threadIdx.x;
    if (i < n) counts[i] = 0;
}

__global__ void hist_kernel(const int* __restrict__ rows, int* __restrict__ counts, int E)
{
    int i = blockIdx.x * blockDim.x + threadIdx.x;
    int stride = gridDim.x * blockDim.x;
    for (; i < E; i += stride) atomicAdd(&counts[__ldcs(&rows[i])], 1);
}

__global__ void __launch_bounds__(1024) scan_pass1(
    const int* __restrict__ counts,
    int* __restrict__ offsets,
    int* __restrict__ blocksums, int n)
{
    __shared__ int sdata[SCAN_CHUNK];
    int tid = threadIdx.x;
    int i = blockIdx.x * SCAN_CHUNK + tid;
    int x = (i < n) ? counts[i] : 0;
    sdata[tid] = x;
    __syncthreads();
#pragma unroll
    for (int off = 1; off < SCAN_CHUNK; off <<= 1) {
        int t = (tid >= off) ? sdata[tid - off] : 0;
        __syncthreads();
        sdata[tid] += t;
        __syncthreads();
    }
    if (i < n) offsets[i] = sdata[tid] - x;   // local exclusive
    if (tid == SCAN_CHUNK - 1) blocksums[blockIdx.x] = sdata[tid];
}

__global__ void scan_pass2(int* __restrict__ blocksums, int* __restrict__ total_out, int nchunks)
{
    __shared__ int sdata[128];
    int tid = threadIdx.x;
    int x = (tid < nchunks) ? blocksums[tid] : 0;
    sdata[tid] = x;
    __syncthreads();
#pragma unroll
    for (int off = 1; off < 128; off <<= 1) {
        int t = (tid >= off) ? sdata[tid - off] : 0;
        __syncthreads();
        sdata[tid] += t;
        __syncthreads();
    }
    if (tid < nchunks) blocksums[tid] = sdata[tid] - x;  // exclusive
    if (tid == 127) *total_out = sdata[127];
}

__global__ void __launch_bounds__(1024) scan_pass3(
    int* __restrict__ offsets,
    int* __restrict__ cursor,
    const int* __restrict__ blocksums, int n)
{
    int i = blockIdx.x * SCAN_CHUNK + threadIdx.x;
    if (i < n) {
        int v = offsets[i] + blocksums[blockIdx.x];
        offsets[i] = v;
        cursor[i] = v;
    }
}

__global__ void scatter_kernel(const int* __restrict__ rows,
                               const int* __restrict__ cols,
                               const float* __restrict__ vals,
                               int* __restrict__ cursor,
                               int2* __restrict__ edata, int E)
{
    int i = blockIdx.x * blockDim.x + threadIdx.x;
    int stride = gridDim.x * blockDim.x;
    for (; i < E; i += stride) {
        int r = __ldcs(&rows[i]);
        int pos = atomicAdd(&cursor[r], 1);
        edata[pos] = make_int2(__ldcs(&cols[i]), __float_as_int(__ldcs(&vals[i])));
    }
}

// ---------------------------------------------------------------------------
// Stage 3: warp-per-node segmented reduction (fp16 gather, fp32 accum).
// ---------------------------------------------------------------------------
__global__ void __launch_bounds__(256) gather_reduce_kernel(
    const int* __restrict__ offsets,
    const int2* __restrict__ edata,
    const __half* __restrict__ sup,
    const float* __restrict__ bias,
    float* __restrict__ out,
    int M)
{
    int warp = (int)((blockIdx.x * blockDim.x + threadIdx.x) >> 5);
    int lane = threadIdx.x & 31;
    if (warp >= M) return;

    int start = offsets[warp];
    int end   = offsets[warp + 1];

    float acc[8];
#pragma unroll
    for (int j = 0; j < 8; j++) acc[j] = 0.0f;

    int e = start;
    for (; e + 1 < end; e += 2) {
        int2 ed0 = __ldcs(&edata[e]);
        int2 ed1 = __ldcs(&edata[e + 1]);
        float v0 = __int_as_float(ed0.y);
        float v1 = __int_as_float(ed1.y);
        uint4 p0 = reinterpret_cast<const uint4*>(sup + (size_t)ed0.x * F_OUT)[lane];
        uint4 p1 = reinterpret_cast<const uint4*>(sup + (size_t)ed1.x * F_OUT)[lane];
        const __half2* h0 = reinterpret_cast<const __half2*>(&p0);
        const __half2* h1 = reinterpret_cast<const __half2*>(&p1);
#pragma unroll
        for (int j = 0; j < 4; j++) {
            float2 f0 = __half22float2(h0[j]);
            float2 f1 = __half22float2(h1[j]);
            acc[2 * j]     = fmaf(v0, f0.x, acc[2 * j]);
            acc[2 * j + 1] = fmaf(v0, f0.y, acc[2 * j + 1]);
            acc[2 * j]     = fmaf(v1, f1.x, acc[2 * j]);
            acc[2 * j + 1] = fmaf(v1, f1.y, acc[2 * j + 1]);
        }
    }
    if (e < end) {
        int2 ed = __ldcs(&edata[e]);
        float v = __int_as_float(ed.y);
        uint4 p = reinterpret_cast<const uint4*>(sup + (size_t)ed.x * F_OUT)[lane];
        const __half2* h = reinterpret_cast<const __half2*>(&p);
#pragma unroll
        for (int j = 0; j < 4; j++) {
            float2 f = __half22float2(h[j]);
            acc[2 * j]     = fmaf(v, f.x, acc[2 * j]);
            acc[2 * j + 1] = fmaf(v, f.y, acc[2 * j + 1]);
        }
    }

    const float4* b4 = reinterpret_cast<const float4*>(bias) + lane * 2;
    float4 bb0 = b4[0];
    float4 bb1 = b4[1];
    float4 o0 = make_float4(acc[0] + bb0.x, acc[1] + bb0.y, acc[2] + bb0.z, acc[3] + bb0.w);
    float4 o1 = make_float4(acc[4] + bb1.x, acc[5] + bb1.y, acc[6] + bb1.z, acc[7] + bb1.w);

    float4* orow = reinterpret_cast<float4*>(out + (size_t)warp * F_OUT) + lane * 2;
    __stcs(&orow[0], o0);
    __stcs(&orow[1], o1);
}

// ---------------------------------------------------------------------------
extern "C" void kernel_launch(void* const* d_in, const int* in_sizes, int n_in,
                              void* d_out, int out_size)
{
    const float* x     = (const float*)d_in[0];
    const int*   erows = (const int*)d_in[1];
    const int*   ecols = (const int*)d_in[2];
    const float* evals = (const float*)d_in[3];
    const float* w     = (const float*)d_in[4];
    const float* b     = (const float*)d_in[5];
    float* out = (float*)d_out;

    const int M = in_sizes[0] / F_IN;     // 100000
    const int E = in_sizes[1];            // 3200000

    __half* sup;
    int2* edata;
    int *counts, *offsets, *cursor, *blocksums;
    cudaGetSymbolAddress((void**)&sup,       g_support_h);
    cudaGetSymbolAddress((void**)&edata,     g_edata);
    cudaGetSymbolAddress((void**)&counts,    g_counts);
    cudaGetSymbolAddress((void**)&offsets,   g_offsets);
    cudaGetSymbolAddress((void**)&cursor,    g_cursor);
    cudaGetSymbolAddress((void**)&blocksums, g_blocksums);

    // Stage 1: TF32 tensor-core GEMM -> fp16 support
    {
        dim3 grid(F_OUT / GBN, (M + GBM - 1) / GBM);
        gemm_tc_kernel<<<grid, 256>>>(x, w, sup, M);
    }

    // Stage 2: counting sort of edges by row
    const int nchunks = (M + SCAN_CHUNK - 1) / SCAN_CHUNK;
    zero_counts_kernel<<<(M + 255) / 256, 256>>>(counts, M);
    hist_kernel<<<1184, 256>>>(erows, counts, E);
    scan_pass1<<<nchunks, SCAN_CHUNK>>>(counts, offsets, blocksums, M);
    scan_pass2<<<1, 128>>>(blocksums, offsets + M, nchunks);
    scan_pass3<<<nchunks, SCAN_CHUNK>>>(offsets, cursor, blocksums, M);
    scatter_kernel<<<1184, 256>>>(erows, ecols, evals, cursor, edata, E);

    // Stage 3: warp-per-node reduction
    {
        int warpsPerBlock = 8;
        int blocks = (M + warpsPerBlock - 1) / warpsPerBlock;
        gather_reduce_kernel<<<blocks, 256>>>(offsets, edata, sup, b, out, M);
    }
}

// round 9
// speedup vs baseline: 7.8051x; 1.0417x over previous
#include <cuda_runtime.h>
#include <cuda_fp16.h>
#include <cuda_bf16.h>
#include <cstdint>

#define N_NODES 100000
#define F_IN 256
#define F_OUT 256
#define MAX_E 3200000

#define SCAN_CHUNK 1024
#define N_CHUNKS ((N_NODES + SCAN_CHUNK - 1) / SCAN_CHUNK)   // 98

// ---- device scratch ----
__device__ __half g_support_h[(size_t)N_NODES * F_OUT];  // 51.2 MB (fp16)
__device__ int2   g_edata[MAX_E];                        // packed (col, val)
__device__ int    g_counts[N_NODES];
__device__ int    g_offsets[N_NODES + 1];
__device__ int    g_cursor[N_NODES];
__device__ int    g_blocksums[N_CHUNKS];

// ---------------------------------------------------------------------------
// Stage 1: TF32 tensor-core GEMM  C[M,256] = A[M,256] @ B[256,256]
// ---------------------------------------------------------------------------
#define GBM 128
#define GBN 128
#define GBK 32
#define AS_STRIDE 36
#define BS_STRIDE 136

__device__ __forceinline__ uint32_t f32_to_tf32(float f)
{
    uint32_t u;
    asm volatile("cvt.rna.tf32.f32 %0, %1;" : "=r"(u) : "f"(f));
    return u;
}

__device__ __forceinline__ void mma_tf32(
    float& d0, float& d1, float& d2, float& d3,
    uint32_t a0, uint32_t a1, uint32_t a2, uint32_t a3,
    uint32_t b0, uint32_t b1)
{
    asm volatile(
        "mma.sync.aligned.m16n8k8.row.col.f32.tf32.tf32.f32 "
        "{%0,%1,%2,%3}, {%4,%5,%6,%7}, {%8,%9}, {%0,%1,%2,%3};\n"
        : "+f"(d0), "+f"(d1), "+f"(d2), "+f"(d3)
        : "r"(a0), "r"(a1), "r"(a2), "r"(a3), "r"(b0), "r"(b1));
}

__global__ void __launch_bounds__(256) gemm_tc_kernel(
    const float* __restrict__ A,
    const float* __restrict__ B,
    __half* __restrict__ C,
    int M)
{
    __shared__ uint32_t As[GBM][AS_STRIDE];
    __shared__ uint32_t Bs[GBK][BS_STRIDE];

    const int tid = threadIdx.x;
    const int lane = tid & 31;
    const int warp = tid >> 5;
    const int warpRow = warp >> 2;
    const int warpCol = warp & 3;
    const int blockRow = blockIdx.y * GBM;
    const int blockCol = blockIdx.x * GBN;

    const int lq = lane >> 2;
    const int lr = lane & 3;

    float d[4][4][4];
#pragma unroll
    for (int mt = 0; mt < 4; mt++)
#pragma unroll
        for (int nt = 0; nt < 4; nt++)
#pragma unroll
            for (int r = 0; r < 4; r++) d[mt][nt][r] = 0.0f;

    for (int k0 = 0; k0 < F_IN; k0 += GBK) {
#pragma unroll
        for (int i = 0; i < 4; i++) {
            int idx = tid + i * 256;
            int row = idx >> 3;
            int kc = (idx & 7) * 4;
            int gr = blockRow + row;
            float4 a4 = make_float4(0.f, 0.f, 0.f, 0.f);
            if (gr < M)
                a4 = *reinterpret_cast<const float4*>(A + (size_t)gr * F_IN + k0 + kc);
            uint4 t;
            t.x = f32_to_tf32(a4.x);
            t.y = f32_to_tf32(a4.y);
            t.z = f32_to_tf32(a4.z);
            t.w = f32_to_tf32(a4.w);
            *reinterpret_cast<uint4*>(&As[row][kc]) = t;
        }
#pragma unroll
        for (int i = 0; i < 4; i++) {
            int idx = tid + i * 256;
            int row = idx >> 5;
            int cc = (idx & 31) * 4;
            float4 b4 = *reinterpret_cast<const float4*>(
                B + (size_t)(k0 + row) * F_OUT + blockCol + cc);
            uint4 t;
            t.x = f32_to_tf32(b4.x);
            t.y = f32_to_tf32(b4.y);
            t.z = f32_to_tf32(b4.z);
            t.w = f32_to_tf32(b4.w);
            *reinterpret_cast<uint4*>(&Bs[row][cc]) = t;
        }
        __syncthreads();

#pragma unroll
        for (int kk = 0; kk < GBK; kk += 8) {
            uint32_t af[4][4];
#pragma unroll
            for (int mt = 0; mt < 4; mt++) {
                int r0 = warpRow * 64 + mt * 16 + lq;
                af[mt][0] = As[r0][kk + lr];
                af[mt][1] = As[r0 + 8][kk + lr];
                af[mt][2] = As[r0][kk + lr + 4];
                af[mt][3] = As[r0 + 8][kk + lr + 4];
            }
            uint32_t bf[4][2];
#pragma unroll
            for (int nt = 0; nt < 4; nt++) {
                int n0 = warpCol * 32 + nt * 8 + lq;
                bf[nt][0] = Bs[kk + lr][n0];
                bf[nt][1] = Bs[kk + lr + 4][n0];
            }
#pragma unroll
            for (int mt = 0; mt < 4; mt++)
#pragma unroll
                for (int nt = 0; nt < 4; nt++)
                    mma_tf32(d[mt][nt][0], d[mt][nt][1], d[mt][nt][2], d[mt][nt][3],
                             af[mt][0], af[mt][1], af[mt][2], af[mt][3],
                             bf[nt][0], bf[nt][1]);
        }
        __syncthreads();
    }

#pragma unroll
    for (int mt = 0; mt < 4; mt++) {
        int r0 = blockRow + warpRow * 64 + mt * 16 + lq;
        int r1 = r0 + 8;
#pragma unroll
        for (int nt = 0; nt < 4; nt++) {
            int c = blockCol + warpCol * 32 + nt * 8 + 2 * lr;
            if (r0 < M)
                *reinterpret_cast<__half2*>(C + (size_t)r0 * F_OUT + c) =
                    __floats2half2_rn(d[mt][nt][0], d[mt][nt][1]);
            if (r1 < M)
                *reinterpret_cast<__half2*>(C + (size_t)r1 * F_OUT + c) =
                    __floats2half2_rn(d[mt][nt][2], d[mt][nt][3]);
        }
    }
}

// ---------------------------------------------------------------------------
// Counting sort of edges by row
// ---------------------------------------------------------------------------
__global__ void zero_counts_kernel(int* __restrict__ counts, int n)
{
    int i = blockIdx.x * blockDim.x + threadIdx.x;
    if (i < n) counts[i] = 0;
}

// vectorized histogram: 4 rows per thread per step (E % 4 == 0)
__global__ void hist_kernel(const int* __restrict__ rows, int* __restrict__ counts, int E)
{
    const int4* r4 = reinterpret_cast<const int4*>(rows);
    int n4 = E >> 2;
    int i = blockIdx.x * blockDim.x + threadIdx.x;
    int stride = gridDim.x * blockDim.x;
    for (; i < n4; i += stride) {
        int4 r = __ldcs(&r4[i]);
        atomicAdd(&counts[r.x], 1);
        atomicAdd(&counts[r.y], 1);
        atomicAdd(&counts[r.z], 1);
        atomicAdd(&counts[r.w], 1);
    }
    // tail (E not multiple of 4)
    int t = n4 * 4 + (blockIdx.x * blockDim.x + threadIdx.x);
    if (t < E) atomicAdd(&counts[rows[t]], 1);
}

__global__ void __launch_bounds__(1024) scan_pass1(
    const int* __restrict__ counts,
    int* __restrict__ offsets,
    int* __restrict__ blocksums, int n)
{
    __shared__ int sdata[SCAN_CHUNK];
    int tid = threadIdx.x;
    int i = blockIdx.x * SCAN_CHUNK + tid;
    int x = (i < n) ? counts[i] : 0;
    sdata[tid] = x;
    __syncthreads();
#pragma unroll
    for (int off = 1; off < SCAN_CHUNK; off <<= 1) {
        int t = (tid >= off) ? sdata[tid - off] : 0;
        __syncthreads();
        sdata[tid] += t;
        __syncthreads();
    }
    if (i < n) offsets[i] = sdata[tid] - x;
    if (tid == SCAN_CHUNK - 1) blocksums[blockIdx.x] = sdata[tid];
}

__global__ void scan_pass2(int* __restrict__ blocksums, int* __restrict__ total_out, int nchunks)
{
    __shared__ int sdata[128];
    int tid = threadIdx.x;
    int x = (tid < nchunks) ? blocksums[tid] : 0;
    sdata[tid] = x;
    __syncthreads();
#pragma unroll
    for (int off = 1; off < 128; off <<= 1) {
        int t = (tid >= off) ? sdata[tid - off] : 0;
        __syncthreads();
        sdata[tid] += t;
        __syncthreads();
    }
    if (tid < nchunks) blocksums[tid] = sdata[tid] - x;
    if (tid == 127) *total_out = sdata[127];
}

__global__ void __launch_bounds__(1024) scan_pass3(
    int* __restrict__ offsets,
    int* __restrict__ cursor,
    const int* __restrict__ blocksums, int n)
{
    int i = blockIdx.x * SCAN_CHUNK + threadIdx.x;
    if (i < n) {
        int v = offsets[i] + blocksums[blockIdx.x];
        offsets[i] = v;
        cursor[i] = v;
    }
}

// vectorized scatter: 4 edges per thread per step
__global__ void scatter_kernel(const int* __restrict__ rows,
                               const int* __restrict__ cols,
                               const float* __restrict__ vals,
                               int* __restrict__ cursor,
                               int2* __restrict__ edata, int E)
{
    const int4*   r4 = reinterpret_cast<const int4*>(rows);
    const int4*   c4 = reinterpret_cast<const int4*>(cols);
    const float4* v4 = reinterpret_cast<const float4*>(vals);
    int n4 = E >> 2;
    int i = blockIdx.x * blockDim.x + threadIdx.x;
    int stride = gridDim.x * blockDim.x;
    for (; i < n4; i += stride) {
        int4   r = __ldcs(&r4[i]);
        int4   c = __ldcs(&c4[i]);
        float4 v = __ldcs(&v4[i]);
        int p0 = atomicAdd(&cursor[r.x], 1);
        int p1 = atomicAdd(&cursor[r.y], 1);
        int p2 = atomicAdd(&cursor[r.z], 1);
        int p3 = atomicAdd(&cursor[r.w], 1);
        edata[p0] = make_int2(c.x, __float_as_int(v.x));
        edata[p1] = make_int2(c.y, __float_as_int(v.y));
        edata[p2] = make_int2(c.z, __float_as_int(v.z));
        edata[p3] = make_int2(c.w, __float_as_int(v.w));
    }
    int t = n4 * 4 + (blockIdx.x * blockDim.x + threadIdx.x);
    if (t < E) {
        int r = rows[t];
        int pos = atomicAdd(&cursor[r], 1);
        edata[pos] = make_int2(cols[t], __float_as_int(vals[t]));
    }
}

// ---------------------------------------------------------------------------
// Stage 3: warp-per-node segmented reduction, 4-edge unroll (MLP=4).
// ---------------------------------------------------------------------------
__device__ __forceinline__ void acc_edge(float (&acc)[8], float v, const uint4& p)
{
    const __half2* h = reinterpret_cast<const __half2*>(&p);
#pragma unroll
    for (int j = 0; j < 4; j++) {
        float2 f = __half22float2(h[j]);
        acc[2 * j]     = fmaf(v, f.x, acc[2 * j]);
        acc[2 * j + 1] = fmaf(v, f.y, acc[2 * j + 1]);
    }
}

__global__ void __launch_bounds__(256) gather_reduce_kernel(
    const int* __restrict__ offsets,
    const int2* __restrict__ edata,
    const __half* __restrict__ sup,
    const float* __restrict__ bias,
    float* __restrict__ out,
    int M)
{
    int warp = (int)((blockIdx.x * blockDim.x + threadIdx.x) >> 5);
    int lane = threadIdx.x & 31;
    if (warp >= M) return;

    int start = offsets[warp];
    int end   = offsets[warp + 1];

    float acc[8];
#pragma unroll
    for (int j = 0; j < 8; j++) acc[j] = 0.0f;

    int e = start;
    int e4end = start + ((end - start) & ~3);
    for (; e < e4end; e += 4) {
        int2 ed0 = __ldcs(&edata[e]);
        int2 ed1 = __ldcs(&edata[e + 1]);
        int2 ed2 = __ldcs(&edata[e + 2]);
        int2 ed3 = __ldcs(&edata[e + 3]);
        uint4 p0 = reinterpret_cast<const uint4*>(sup + (size_t)ed0.x * F_OUT)[lane];
        uint4 p1 = reinterpret_cast<const uint4*>(sup + (size_t)ed1.x * F_OUT)[lane];
        uint4 p2 = reinterpret_cast<const uint4*>(sup + (size_t)ed2.x * F_OUT)[lane];
        uint4 p3 = reinterpret_cast<const uint4*>(sup + (size_t)ed3.x * F_OUT)[lane];
        acc_edge(acc, __int_as_float(ed0.y), p0);
        acc_edge(acc, __int_as_float(ed1.y), p1);
        acc_edge(acc, __int_as_float(ed2.y), p2);
        acc_edge(acc, __int_as_float(ed3.y), p3);
    }
    for (; e < end; e++) {
        int2 ed = __ldcs(&edata[e]);
        uint4 p = reinterpret_cast<const uint4*>(sup + (size_t)ed.x * F_OUT)[lane];
        acc_edge(acc, __int_as_float(ed.y), p);
    }

    const float4* b4 = reinterpret_cast<const float4*>(bias) + lane * 2;
    float4 bb0 = b4[0];
    float4 bb1 = b4[1];
    float4 o0 = make_float4(acc[0] + bb0.x, acc[1] + bb0.y, acc[2] + bb0.z, acc[3] + bb0.w);
    float4 o1 = make_float4(acc[4] + bb1.x, acc[5] + bb1.y, acc[6] + bb1.z, acc[7] + bb1.w);

    float4* orow = reinterpret_cast<float4*>(out + (size_t)warp * F_OUT) + lane * 2;
    __stcs(&orow[0], o0);
    __stcs(&orow[1], o1);
}

// ---------------------------------------------------------------------------
extern "C" void kernel_launch(void* const* d_in, const int* in_sizes, int n_in,
                              void* d_out, int out_size)
{
    const float* x     = (const float*)d_in[0];
    const int*   erows = (const int*)d_in[1];
    const int*   ecols = (const int*)d_in[2];
    const float* evals = (const float*)d_in[3];
    const float* w     = (const float*)d_in[4];
    const float* b     = (const float*)d_in[5];
    float* out = (float*)d_out;

    const int M = in_sizes[0] / F_IN;     // 100000
    const int E = in_sizes[1];            // 3200000

    __half* sup;
    int2* edata;
    int *counts, *offsets, *cursor, *blocksums;
    cudaGetSymbolAddress((void**)&sup,       g_support_h);
    cudaGetSymbolAddress((void**)&edata,     g_edata);
    cudaGetSymbolAddress((void**)&counts,    g_counts);
    cudaGetSymbolAddress((void**)&offsets,   g_offsets);
    cudaGetSymbolAddress((void**)&cursor,    g_cursor);
    cudaGetSymbolAddress((void**)&blocksums, g_blocksums);

    // Stage 1: TF32 tensor-core GEMM -> fp16 support
    {
        dim3 grid(F_OUT / GBN, (M + GBM - 1) / GBM);
        gemm_tc_kernel<<<grid, 256>>>(x, w, sup, M);
    }

    // Stage 2: counting sort of edges by row
    const int nchunks = (M + SCAN_CHUNK - 1) / SCAN_CHUNK;
    zero_counts_kernel<<<(M + 255) / 256, 256>>>(counts, M);
    hist_kernel<<<592, 256>>>(erows, counts, E);
    scan_pass1<<<nchunks, SCAN_CHUNK>>>(counts, offsets, blocksums, M);
    scan_pass2<<<1, 128>>>(blocksums, offsets + M, nchunks);
    scan_pass3<<<nchunks, SCAN_CHUNK>>>(offsets, cursor, blocksums, M);
    scatter_kernel<<<592, 256>>>(erows, ecols, evals, cursor, edata, E);

    // Stage 3: warp-per-node reduction
    {
        int warpsPerBlock = 8;
        int blocks = (M + warpsPerBlock - 1) / warpsPerBlock;
        gather_reduce_kernel<<<blocks, 256>>>(offsets, edata, sup, b, out, M);
    }
}